// round 9
// baseline (speedup 1.0000x reference)
#include <cuda_runtime.h>
#include <cuda_fp16.h>
#include <cstdint>

#define DEVINL static __device__ __forceinline__

// ---------------- problem dims ----------------
#define B_SZ   8192
#define KTOT   2048           // IN + H fused K
#define NOUT   4096           // 4 gates x 1024
#define NTHREADS 512
#define NSTAGE 3
#define KSTAGE 64             // K per stage
#define NIT    (KTOT / KSTAGE)   // 32

// smem per stage: A 128 rows x 64 k x fp16 = 16KB, B 256 cols x 64 k x fp16 = 32KB
#define STAGE_BYTES (48 * 1024)
#define B_OFF       (16 * 1024)
#define SMEM_TOTAL  (NSTAGE * STAGE_BYTES)   // 147456

// scratch (device globals: allocation-free rule), fp16 fragment-order
__device__ uint4 g_A[(size_t)B_SZ * KTOT / 8];     // 32 MB  [mb64][kt16_128][mt8][lane32]
__device__ uint2 g_B[(size_t)NOUT * KTOT / 4];     // 16 MB  [nb16][kt16_128][nt32][lane32]

// ---------------- helpers ----------------
DEVINL uint32_t smem_u32(const void* p){
  uint32_t a; asm("{ .reg .u64 t; cvta.to.shared.u64 t, %1; cvt.u32.u64 %0, t; }" : "=r"(a) : "l"(p)); return a;
}
DEVINL void cp16(uint32_t dst, const void* src){
  asm volatile("cp.async.cg.shared.global [%0], [%1], 16;" :: "r"(dst), "l"(src));
}
DEVINL void cp_commit(){ asm volatile("cp.async.commit_group;"); }
template<int N> DEVINL void cp_wait(){ asm volatile("cp.async.wait_group %0;" :: "n"(N)); }

DEVINL void mma16(float* d, const uint4& a, uint32_t b0, uint32_t b1){
  asm volatile(
    "mma.sync.aligned.m16n8k16.row.col.f32.f16.f16.f32 "
    "{%0,%1,%2,%3}, {%4,%5,%6,%7}, {%8,%9}, {%0,%1,%2,%3};"
    : "+f"(d[0]), "+f"(d[1]), "+f"(d[2]), "+f"(d[3])
    : "r"(a.x), "r"(a.y), "r"(a.z), "r"(a.w), "r"(b0), "r"(b1));
}
DEVINL float sigmoidf_(float x){ return 1.f / (1.f + __expf(-x)); }
DEVINL uint32_t pack2(float lo, float hi){
  __half2 v = __floats2half2_rn(lo, hi);
  return *reinterpret_cast<uint32_t*>(&v);
}

// ---------------- prep A ----------------
// m16n8k16 A-fragment order: idx = ((mb*128 + kt16)*8 + mt)*32 + lane
//   r = mb*128 + mt*16 + lane/4,  k = kt16*16 + (lane%4)*2,  A = [x | h]
__global__ void prep_A(const float* __restrict__ x, const float* __restrict__ h){
  size_t idx = (size_t)blockIdx.x * 256 + threadIdx.x;   // [0, 2097152)
  int lane = (int)(idx & 31);
  int mt   = (int)((idx >> 5) & 7);
  int kt   = (int)((idx >> 8) & 127);
  int mb   = (int)(idx >> 15);
  int r = mb * 128 + mt * 16 + (lane >> 2);
  int k = kt * 16 + (lane & 3) * 2;
  const float* src = (k < 1024) ? x : h;
  int ko = k & 1023;
  const float* p0 = src + (size_t)r * 1024 + ko;
  const float* p1 = src + (size_t)(r + 8) * 1024 + ko;
  uint4 v;
  v.x = pack2(p0[0], p0[1]);
  v.y = pack2(p1[0], p1[1]);
  v.z = pack2(p0[8], p0[9]);
  v.w = pack2(p1[8], p1[9]);
  g_A[idx] = v;
}

// ---------------- prep B ----------------
// m16n8k16 B-fragment order: idx = ((nb*128 + kt16)*32 + nt)*32 + lane
//   gate interleave: g = nt&3, cb = nt>>2
//   n = g*1024 + nb*64 + cb*8 + lane/4,  k = kt16*16 + (lane%4)*2,  W = [Wx ; Wh]
__global__ void prep_B(const float* __restrict__ Wx, const float* __restrict__ Wh){
  size_t idx = (size_t)blockIdx.x * 256 + threadIdx.x;   // [0, 2097152)
  int lane = (int)(idx & 31);
  int nt   = (int)((idx >> 5) & 31);
  int kt   = (int)((idx >> 10) & 127);
  int nb   = (int)(idx >> 17);
  int g = nt & 3, cb = nt >> 2;
  int n  = g * 1024 + nb * 64 + cb * 8 + (lane >> 2);
  int k0 = kt * 16 + (lane & 3) * 2;
  const float* W = (k0 < 1024) ? Wx : Wh;
  int k = k0 & 1023;
  uint2 v;
  v.x = pack2(W[(size_t)k       * 4096 + n], W[(size_t)(k + 1) * 4096 + n]);
  v.y = pack2(W[(size_t)(k + 8) * 4096 + n], W[(size_t)(k + 9) * 4096 + n]);
  g_B[idx] = v;
}

// ---------------- main fused GEMM + LSTM ----------------
// 512 threads = 16 warps as 4x4 grid; warp tile 32 rows x 64 permuted cols.
// 3-stage ring, K=64/stage; loads for stage st+2 issued (spread) during stage st,
// so each stage's data has a FULL stage (~2k cyc) to land before its cp_wait.
__global__ void __launch_bounds__(NTHREADS, 1)
lstm_main(const float* __restrict__ c,
          const float* __restrict__ bx, const float* __restrict__ bh,
          float* __restrict__ out)
{
  extern __shared__ char smem[];
  const uint32_t sb = smem_u32(smem);
  const int tid = threadIdx.x;
  const int w   = tid >> 5;
  const int T   = tid & 31;
  const int w_m = w >> 2;          // 0..3 (32 rows each)
  const int w_n = w & 3;           // 0..3 (8 nt tiles each)
  const int nb  = blockIdx.x;      // 16
  const int mb  = blockIdx.y;      // 64

  // per-CTA bases; per stage (4 kt16): A = 1024 uint4, B = 4096 uint2 (contiguous)
  const uint4* gA = g_A + (size_t)mb * 32768;
  const uint2* gB = g_B + (size_t)nb * 131072;

  // per-thread load slots per stage: 2 x A (uint4) + 4 x B (uint2-pair) = 6 cp16
  auto issue_slot = [&](uint32_t base, const uint4* srcA, const uint2* srcB, int sl){
    if (sl < 2)
      cp16(base + (tid + sl * 512) * 16, srcA + tid + sl * 512);
    else
      cp16(base + B_OFF + (tid + (sl - 2) * 512) * 16, srcB + 2 * (tid + (sl - 2) * 512));
  };
  auto load_burst = [&](int st){
    uint32_t base = sb + (st % NSTAGE) * STAGE_BYTES;
    const uint4* srcA = gA + (size_t)st * 1024;
    const uint2* srcB = gB + (size_t)st * 4096;
    #pragma unroll
    for (int sl = 0; sl < 6; ++sl) issue_slot(base, srcA, srcB, sl);
  };

  float acc[2][8][4];
  #pragma unroll
  for (int a = 0; a < 2; ++a)
    #pragma unroll
    for (int b = 0; b < 8; ++b)
      #pragma unroll
      for (int q = 0; q < 4; ++q) acc[a][b][q] = 0.f;

  // prologue: G_0 and G_1 in flight as separate groups
  load_burst(0); cp_commit();
  load_burst(1); cp_commit();

  for (int st = 0; st < NIT; ++st){
    cp_wait<1>();      // G_st done (G_{st+1} may remain in flight)
    __syncthreads();   // all warps finished stage st-1 -> buffer (st+2)%3 free

    const uint4* As = (const uint4*)(smem + (st % NSTAGE) * STAGE_BYTES);
    const uint2* Bs = (const uint2*)(smem + (st % NSTAGE) * STAGE_BYTES + B_OFF);

    const bool pf = (st + 2 < NIT);
    uint32_t nbase = sb + ((st + 2) % NSTAGE) * STAGE_BYTES;
    const uint4* nA = gA + (size_t)(st + 2) * 1024;
    const uint2* nB = gB + (size_t)(st + 2) * 4096;

    #pragma unroll
    for (int kt = 0; kt < 4; ++kt){
      // spread next+1-stage cp.async: 2,2,1,1 slots over the 4 kt iterations
      if (pf){
        if (kt == 0){ issue_slot(nbase, nA, nB, 0); issue_slot(nbase, nA, nB, 1); }
        else if (kt == 1){ issue_slot(nbase, nA, nB, 2); issue_slot(nbase, nA, nB, 3); }
        else if (kt == 2){ issue_slot(nbase, nA, nB, 4); }
        else { issue_slot(nbase, nA, nB, 5); }
      }

      uint2 bf[8];
      #pragma unroll
      for (int j = 0; j < 8; ++j)
        bf[j] = Bs[(kt * 32 + w_n * 8 + j) * 32 + T];
      uint4 af[2];
      #pragma unroll
      for (int mt = 0; mt < 2; ++mt)
        af[mt] = As[(kt * 8 + w_m * 2 + mt) * 32 + T];
      #pragma unroll
      for (int mt = 0; mt < 2; ++mt)
        #pragma unroll
        for (int j = 0; j < 8; ++j)
          mma16(acc[mt][j], af[mt], bf[j].x, bf[j].y);
    }
    cp_commit();   // close group G_{st+2} (empty near the end; keeps accounting aligned)
  }

  // -------- fused LSTM epilogue (register-local: gates g at acc[.][jc*4+g]) --------
  const size_t S = (size_t)B_SZ * 1024;

  float bias[2][4][2];
  #pragma unroll
  for (int jc = 0; jc < 2; ++jc){
    int col = nb * 64 + (w_n * 2 + jc) * 8 + (T & 3) * 2;
    #pragma unroll
    for (int g = 0; g < 4; ++g)
      #pragma unroll
      for (int cc = 0; cc < 2; ++cc)
        bias[jc][g][cc] = bx[g * 1024 + col + cc] + bh[g * 1024 + col + cc];
  }

  #pragma unroll
  for (int mt = 0; mt < 2; ++mt){
    #pragma unroll
    for (int jc = 0; jc < 2; ++jc){
      int col = nb * 64 + (w_n * 2 + jc) * 8 + (T & 3) * 2;
      #pragma unroll
      for (int rr = 0; rr < 2; ++rr){
        int row = mb * 128 + w_m * 32 + mt * 16 + (T >> 2) + rr * 8;
        size_t ro = (size_t)row * 1024 + col;
        float2 cin = *(const float2*)(c + ro);
        float2 o2, h2v, c2;
        #pragma unroll
        for (int cc = 0; cc < 2; ++cc){
          int q = rr * 2 + cc;
          float vi = acc[mt][jc * 4 + 0][q] + bias[jc][0][cc];
          float vf = acc[mt][jc * 4 + 1][q] + bias[jc][1][cc];
          float vg = acc[mt][jc * 4 + 2][q] + bias[jc][2][cc];
          float vo = acc[mt][jc * 4 + 3][q] + bias[jc][3][cc];
          float ig = sigmoidf_(vi);
          float fg = sigmoidf_(vf);
          float gg = tanhf(vg);
          float og = sigmoidf_(vo);
          float cv = (cc == 0) ? cin.x : cin.y;
          float cn = fg * cv + ig * gg;
          float hn = og * tanhf(cn);
          if (cc == 0){ o2.x = og; h2v.x = hn; c2.x = cn; }
          else        { o2.y = og; h2v.y = hn; c2.y = cn; }
        }
        *(float2*)(out + ro)         = o2;    // output gate
        *(float2*)(out + S + ro)     = h2v;   // h_new
        *(float2*)(out + 2 * S + ro) = c2;    // c_new
      }
    }
  }
}

// ---------------- launch ----------------
extern "C" void kernel_launch(void* const* d_in, const int* in_sizes, int n_in,
                              void* d_out, int out_size)
{
  const float* x  = (const float*)d_in[0];
  const float* h  = (const float*)d_in[1];
  const float* c  = (const float*)d_in[2];
  const float* Wx = (const float*)d_in[3];
  const float* Wh = (const float*)d_in[4];
  const float* bx = (const float*)d_in[5];
  const float* bh = (const float*)d_in[6];
  float* out = (float*)d_out;

  cudaFuncSetAttribute(lstm_main,
                       cudaFuncAttributeMaxDynamicSharedMemorySize, SMEM_TOTAL);

  prep_A<<<(B_SZ * KTOT / 8) / 256, 256>>>(x, h);          // 8192 blocks
  prep_B<<<(NOUT * KTOT / 4) / 256, 256>>>(Wx, Wh);        // 8192 blocks
  lstm_main<<<dim3(16, 64), NTHREADS, SMEM_TOTAL>>>(c, bx, bh, out);
}

// round 12
// speedup vs baseline: 1.0852x; 1.0852x over previous
#include <cuda_runtime.h>
#include <cuda_fp16.h>
#include <cstdint>

#define DEVINL static __device__ __forceinline__

// ---------------- problem dims ----------------
#define B_SZ   8192
#define KTOT   2048           // IN + H fused K
#define NOUT   4096           // 4 gates x 1024
#define NTHREADS 256
#define NSTAGE 3
#define KSTAGE 64             // K per stage
#define NIT    (KTOT / KSTAGE)   // 32

// smem per stage: A 128 rows x 64 k x fp16 = 16KB, B 128 pcols x 64 k x fp16 = 16KB
#define STAGE_BYTES (32 * 1024)
#define B_OFF       (16 * 1024)
#define SMEM_TOTAL  (NSTAGE * STAGE_BYTES)   // 98304 -> 2 CTAs/SM

// scratch (device globals: allocation-free rule), fp16 fragment-order
__device__ uint4 g_A[(size_t)B_SZ * KTOT / 8];     // 32 MB  [mb64][kt16_128][mt8][lane32]
__device__ uint2 g_B[(size_t)NOUT * KTOT / 4];     // 16 MB  [nb32][kt16_128][nt16][lane32]

// ---------------- helpers ----------------
DEVINL uint32_t smem_u32(const void* p){
  uint32_t a; asm("{ .reg .u64 t; cvta.to.shared.u64 t, %1; cvt.u32.u64 %0, t; }" : "=r"(a) : "l"(p)); return a;
}
DEVINL void cp16(uint32_t dst, const void* src){
  asm volatile("cp.async.cg.shared.global [%0], [%1], 16;" :: "r"(dst), "l"(src));
}
DEVINL void cp_commit(){ asm volatile("cp.async.commit_group;"); }
template<int N> DEVINL void cp_wait(){ asm volatile("cp.async.wait_group %0;" :: "n"(N)); }

DEVINL void mma16(float* d, const uint4& a, uint32_t b0, uint32_t b1){
  asm volatile(
    "mma.sync.aligned.m16n8k16.row.col.f32.f16.f16.f32 "
    "{%0,%1,%2,%3}, {%4,%5,%6,%7}, {%8,%9}, {%0,%1,%2,%3};"
    : "+f"(d[0]), "+f"(d[1]), "+f"(d[2]), "+f"(d[3])
    : "r"(a.x), "r"(a.y), "r"(a.z), "r"(a.w), "r"(b0), "r"(b1));
}
DEVINL float sigmoidf_(float x){ return 1.f / (1.f + __expf(-x)); }
DEVINL uint32_t pack2(float lo, float hi){
  __half2 v = __floats2half2_rn(lo, hi);
  return *reinterpret_cast<uint32_t*>(&v);
}

// ---------------- prep A ----------------
// m16n8k16 A-fragment order: idx = ((mb*128 + kt16)*8 + mt)*32 + lane
//   r = mb*128 + mt*16 + lane/4,  k = kt16*16 + (lane%4)*2,  A = [x | h]
__global__ void prep_A(const float* __restrict__ x, const float* __restrict__ h){
  size_t idx = (size_t)blockIdx.x * 256 + threadIdx.x;   // [0, 2097152)
  int lane = (int)(idx & 31);
  int mt   = (int)((idx >> 5) & 7);
  int kt   = (int)((idx >> 8) & 127);
  int mb   = (int)(idx >> 15);
  int r = mb * 128 + mt * 16 + (lane >> 2);
  int k = kt * 16 + (lane & 3) * 2;
  const float* src = (k < 1024) ? x : h;
  int ko = k & 1023;
  const float* p0 = src + (size_t)r * 1024 + ko;
  const float* p1 = src + (size_t)(r + 8) * 1024 + ko;
  uint4 v;
  v.x = pack2(p0[0], p0[1]);
  v.y = pack2(p1[0], p1[1]);
  v.z = pack2(p0[8], p0[9]);
  v.w = pack2(p1[8], p1[9]);
  g_A[idx] = v;
}

// ---------------- prep B ----------------
// m16n8k16 B-fragment order: idx = ((nb*128 + kt16)*16 + nt)*32 + lane
//   nt = cb*4 + g  (cb = col-block 0..3, g = gate)
//   n = g*1024 + nb*32 + cb*8 + lane/4,  k = kt16*16 + (lane%4)*2,  W = [Wx ; Wh]
__global__ void prep_B(const float* __restrict__ Wx, const float* __restrict__ Wh){
  size_t idx = (size_t)blockIdx.x * 256 + threadIdx.x;   // [0, 2097152)
  int lane = (int)(idx & 31);
  int nt   = (int)((idx >> 5) & 15);
  int kt   = (int)((idx >> 9) & 127);
  int nb   = (int)(idx >> 16);                           // 0..31
  int g = nt & 3, cb = nt >> 2;
  int n  = g * 1024 + nb * 32 + cb * 8 + (lane >> 2);
  int k0 = kt * 16 + (lane & 3) * 2;
  const float* W = (k0 < 1024) ? Wx : Wh;
  int k = k0 & 1023;
  uint2 v;
  v.x = pack2(W[(size_t)k       * 4096 + n], W[(size_t)(k + 1) * 4096 + n]);
  v.y = pack2(W[(size_t)(k + 8) * 4096 + n], W[(size_t)(k + 9) * 4096 + n]);
  g_B[idx] = v;
}

// ---------------- main fused GEMM + LSTM ----------------
// 256 threads = 8 warps as 2x4 grid; warp tile 64 rows x 32 permuted cols
// (= 8 logical cols x 4 gates, register-local epilogue).
// 3-stage K=64 ring, st+2 prefetch; 96KB smem -> 2 CTAs/SM for cross-CTA
// bubble filling at barriers.
__global__ void __launch_bounds__(NTHREADS, 2)
lstm_main(const float* __restrict__ c,
          const float* __restrict__ bx, const float* __restrict__ bh,
          float* __restrict__ out)
{
  extern __shared__ char smem[];
  const uint32_t sb = smem_u32(smem);
  const int tid = threadIdx.x;
  const int w   = tid >> 5;
  const int T   = tid & 31;
  const int w_m = w >> 2;          // 0..1 (64 rows each)
  const int w_n = w & 3;           // 0..3 (one col-block: nt = w_n*4 + g)
  const int nb  = blockIdx.x;      // 32
  const int mb  = blockIdx.y;      // 64

  // per-CTA bases; per stage (4 kt16): A = 1024 uint4, B = 2048 uint2 (contiguous)
  const uint4* gA = g_A + (size_t)mb * 32768;
  const uint2* gB = g_B + (size_t)nb * 65536;

  // per-thread load slots per stage: 4 x A (uint4) + 4 x B (uint2-pair) = 8 cp16
  auto issue_slot = [&](uint32_t base, const uint4* srcA, const uint2* srcB, int sl){
    if (sl < 4)
      cp16(base + (tid + sl * 256) * 16, srcA + tid + sl * 256);
    else
      cp16(base + B_OFF + (tid + (sl - 4) * 256) * 16, srcB + 2 * (tid + (sl - 4) * 256));
  };
  auto load_burst = [&](int st){
    uint32_t base = sb + (st % NSTAGE) * STAGE_BYTES;
    const uint4* srcA = gA + (size_t)st * 1024;
    const uint2* srcB = gB + (size_t)st * 2048;
    #pragma unroll
    for (int sl = 0; sl < 8; ++sl) issue_slot(base, srcA, srcB, sl);
  };

  float acc[4][4][4];   // [mt][gate][q]
  #pragma unroll
  for (int a = 0; a < 4; ++a)
    #pragma unroll
    for (int b = 0; b < 4; ++b)
      #pragma unroll
      for (int q = 0; q < 4; ++q) acc[a][b][q] = 0.f;

  // prologue: G_0 and G_1 in flight as separate groups
  load_burst(0); cp_commit();
  load_burst(1); cp_commit();

  for (int st = 0; st < NIT; ++st){
    cp_wait<1>();      // G_st done (G_{st+1} may remain in flight)
    __syncthreads();   // all warps finished stage st-1 -> buffer (st+2)%3 free

    const uint4* As = (const uint4*)(smem + (st % NSTAGE) * STAGE_BYTES);
    const uint2* Bs = (const uint2*)(smem + (st % NSTAGE) * STAGE_BYTES + B_OFF);

    const bool pf = (st + 2 < NIT);
    uint32_t nbase = sb + ((st + 2) % NSTAGE) * STAGE_BYTES;
    const uint4* nA = gA + (size_t)(st + 2) * 1024;
    const uint2* nB = gB + (size_t)(st + 2) * 2048;

    #pragma unroll
    for (int kt = 0; kt < 4; ++kt){
      // spread next+1-stage cp.async: 2 slots per kt iteration
      if (pf){
        issue_slot(nbase, nA, nB, 2 * kt);
        issue_slot(nbase, nA, nB, 2 * kt + 1);
      }

      uint2 bf[4];
      #pragma unroll
      for (int j = 0; j < 4; ++j)
        bf[j] = Bs[(kt * 16 + w_n * 4 + j) * 32 + T];
      uint4 af[4];
      #pragma unroll
      for (int mt = 0; mt < 4; ++mt)
        af[mt] = As[(kt * 8 + w_m * 4 + mt) * 32 + T];
      #pragma unroll
      for (int mt = 0; mt < 4; ++mt)
        #pragma unroll
        for (int j = 0; j < 4; ++j)
          mma16(acc[mt][j], af[mt], bf[j].x, bf[j].y);
    }
    cp_commit();   // close group G_{st+2} (empty near the end; keeps accounting aligned)
  }

  // -------- fused LSTM epilogue (register-local: gate g at acc[mt][g]) --------
  const size_t S = (size_t)B_SZ * 1024;
  const int col = nb * 32 + w_n * 8 + (T & 3) * 2;

  float bias[4][2];
  #pragma unroll
  for (int g = 0; g < 4; ++g)
    #pragma unroll
    for (int cc = 0; cc < 2; ++cc)
      bias[g][cc] = bx[g * 1024 + col + cc] + bh[g * 1024 + col + cc];

  #pragma unroll
  for (int mt = 0; mt < 4; ++mt){
    #pragma unroll
    for (int rr = 0; rr < 2; ++rr){
      int row = mb * 128 + w_m * 64 + mt * 16 + (T >> 2) + rr * 8;
      size_t ro = (size_t)row * 1024 + col;
      float2 cin = *(const float2*)(c + ro);
      float2 o2, h2v, c2;
      #pragma unroll
      for (int cc = 0; cc < 2; ++cc){
        int q = rr * 2 + cc;
        float vi = acc[mt][0][q] + bias[0][cc];
        float vf = acc[mt][1][q] + bias[1][cc];
        float vg = acc[mt][2][q] + bias[2][cc];
        float vo = acc[mt][3][q] + bias[3][cc];
        float ig = sigmoidf_(vi);
        float fg = sigmoidf_(vf);
        float gg = tanhf(vg);
        float og = sigmoidf_(vo);
        float cv = (cc == 0) ? cin.x : cin.y;
        float cn = fg * cv + ig * gg;
        float hn = og * tanhf(cn);
        if (cc == 0){ o2.x = og; h2v.x = hn; c2.x = cn; }
        else        { o2.y = og; h2v.y = hn; c2.y = cn; }
      }
      *(float2*)(out + ro)         = o2;    // output gate
      *(float2*)(out + S + ro)     = h2v;   // h_new
      *(float2*)(out + 2 * S + ro) = c2;    // c_new
    }
  }
}

// ---------------- launch ----------------
extern "C" void kernel_launch(void* const* d_in, const int* in_sizes, int n_in,
                              void* d_out, int out_size)
{
  const float* x  = (const float*)d_in[0];
  const float* h  = (const float*)d_in[1];
  const float* c  = (const float*)d_in[2];
  const float* Wx = (const float*)d_in[3];
  const float* Wh = (const float*)d_in[4];
  const float* bx = (const float*)d_in[5];
  const float* bh = (const float*)d_in[6];
  float* out = (float*)d_out;

  cudaFuncSetAttribute(lstm_main,
                       cudaFuncAttributeMaxDynamicSharedMemorySize, SMEM_TOTAL);

  prep_A<<<(B_SZ * KTOT / 8) / 256, 256>>>(x, h);          // 8192 blocks
  prep_B<<<(NOUT * KTOT / 4) / 256, 256>>>(Wx, Wh);        // 8192 blocks
  lstm_main<<<dim3(32, 64), NTHREADS, SMEM_TOTAL>>>(c, bx, bh, out);
}

// round 14
// speedup vs baseline: 1.1245x; 1.0362x over previous
#include <cuda_runtime.h>
#include <cuda_fp16.h>
#include <cstdint>

#define DEVINL static __device__ __forceinline__

// ---------------- problem dims ----------------
#define B_SZ   8192
#define KTOT   2048           // IN + H fused K
#define NOUT   4096           // 4 gates x 1024
#define NTHREADS 512
#define NSTAGE 2
#define KSTAGE 128            // K per stage
#define NIT    (KTOT / KSTAGE)   // 16

// smem per stage: A 128 rows x 128 k x fp16 = 32KB, B 256 cols x 128 k x fp16 = 64KB
#define STAGE_BYTES (96 * 1024)
#define B_OFF       (32 * 1024)
#define SMEM_TOTAL  (NSTAGE * STAGE_BYTES)   // 196608

// scratch (device globals: allocation-free rule), fp16 fragment-order
__device__ uint4 g_A[(size_t)B_SZ * KTOT / 8];     // 32 MB  [mb64][kt16_128][mt8][lane32]
__device__ uint2 g_B[(size_t)NOUT * KTOT / 4];     // 16 MB  [nb16][kt16_128][nt32][lane32]

// ---------------- helpers ----------------
DEVINL uint32_t smem_u32(const void* p){
  uint32_t a; asm("{ .reg .u64 t; cvta.to.shared.u64 t, %1; cvt.u32.u64 %0, t; }" : "=r"(a) : "l"(p)); return a;
}
DEVINL void cp16(uint32_t dst, const void* src){
  asm volatile("cp.async.cg.shared.global [%0], [%1], 16;" :: "r"(dst), "l"(src));
}
DEVINL void cp_commit(){ asm volatile("cp.async.commit_group;"); }
template<int N> DEVINL void cp_wait(){ asm volatile("cp.async.wait_group %0;" :: "n"(N)); }

DEVINL void mma16(float* d, const uint4& a, uint32_t b0, uint32_t b1){
  asm volatile(
    "mma.sync.aligned.m16n8k16.row.col.f32.f16.f16.f32 "
    "{%0,%1,%2,%3}, {%4,%5,%6,%7}, {%8,%9}, {%0,%1,%2,%3};"
    : "+f"(d[0]), "+f"(d[1]), "+f"(d[2]), "+f"(d[3])
    : "r"(a.x), "r"(a.y), "r"(a.z), "r"(a.w), "r"(b0), "r"(b1));
}
DEVINL float sigmoidf_(float x){ return 1.f / (1.f + __expf(-x)); }
DEVINL uint32_t pack2(float lo, float hi){
  __half2 v = __floats2half2_rn(lo, hi);
  return *reinterpret_cast<uint32_t*>(&v);
}

// ---------------- merged prep (A and B in ONE launch; overlapping DRAM streams) ----
// A half (blocks [0, 8192)): m16n8k16 A-fragment order
//   idx = ((mb*128 + kt16)*8 + mt)*32 + lane
//   r = mb*128 + mt*16 + lane/4,  k = kt16*16 + (lane%4)*2,  A = [x | h]
// B half (blocks [8192, 16384)): m16n8k16 B-fragment order, gate-interleaved
//   idx = ((nb*128 + kt16)*32 + nt)*32 + lane,  nt: g = nt&3, cb = nt>>2
//   n = g*1024 + nb*64 + cb*8 + lane/4,  k = kt16*16 + (lane%4)*2,  W = [Wx ; Wh]
__global__ void prep_AB(const float* __restrict__ x, const float* __restrict__ h,
                        const float* __restrict__ Wx, const float* __restrict__ Wh){
  if (blockIdx.x < 8192){
    size_t idx = (size_t)blockIdx.x * 256 + threadIdx.x;   // [0, 2097152)
    int lane = (int)(idx & 31);
    int mt   = (int)((idx >> 5) & 7);
    int kt   = (int)((idx >> 8) & 127);
    int mb   = (int)(idx >> 15);
    int r = mb * 128 + mt * 16 + (lane >> 2);
    int k = kt * 16 + (lane & 3) * 2;
    const float* src = (k < 1024) ? x : h;
    int ko = k & 1023;
    const float* p0 = src + (size_t)r * 1024 + ko;
    const float* p1 = src + (size_t)(r + 8) * 1024 + ko;
    uint4 v;
    v.x = pack2(p0[0], p0[1]);
    v.y = pack2(p1[0], p1[1]);
    v.z = pack2(p0[8], p0[9]);
    v.w = pack2(p1[8], p1[9]);
    g_A[idx] = v;
  } else {
    size_t idx = (size_t)(blockIdx.x - 8192) * 256 + threadIdx.x;   // [0, 2097152)
    int lane = (int)(idx & 31);
    int nt   = (int)((idx >> 5) & 31);
    int kt   = (int)((idx >> 10) & 127);
    int nb   = (int)(idx >> 17);
    int g = nt & 3, cb = nt >> 2;
    int n  = g * 1024 + nb * 64 + cb * 8 + (lane >> 2);
    int k0 = kt * 16 + (lane & 3) * 2;
    const float* W = (k0 < 1024) ? Wx : Wh;
    int k = k0 & 1023;
    uint2 v;
    v.x = pack2(W[(size_t)k       * 4096 + n], W[(size_t)(k + 1) * 4096 + n]);
    v.y = pack2(W[(size_t)(k + 8) * 4096 + n], W[(size_t)(k + 9) * 4096 + n]);
    g_B[idx] = v;
  }
}

// ---------------- main fused GEMM + LSTM (R8 config: proven at HMMA-pipe floor) ----
// 512 threads = 16 warps as 4x4 grid; warp tile 32 rows x 64 permuted cols
// 2-stage ring, K=128/stage, cp.async spread through the MMA loop.
__global__ void __launch_bounds__(NTHREADS, 1)
lstm_main(const float* __restrict__ c,
          const float* __restrict__ bx, const float* __restrict__ bh,
          float* __restrict__ out)
{
  extern __shared__ char smem[];
  const uint32_t sb = smem_u32(smem);
  const int tid = threadIdx.x;
  const int w   = tid >> 5;
  const int T   = tid & 31;
  const int w_m = w >> 2;          // 0..3 (32 rows each)
  const int w_n = w & 3;           // 0..3 (8 nt tiles each)
  const int nb  = blockIdx.x;      // 16
  const int mb  = blockIdx.y;      // 64

  // per-CTA bases; per stage (8 kt16): A = 2048 uint4, B = 8192 uint2 (contiguous)
  const uint4* gA = g_A + (size_t)mb * 32768;
  const uint2* gB = g_B + (size_t)nb * 131072;

  auto load_burst = [&](int st){
    uint32_t base = sb + (st & 1) * STAGE_BYTES;
    const uint4* srcA = gA + (size_t)st * 2048;
    #pragma unroll
    for (int j = 0; j < 4; ++j)
      cp16(base + (tid + j * 512) * 16, srcA + tid + j * 512);
    const uint2* srcB = gB + (size_t)st * 8192;
    #pragma unroll
    for (int j = 0; j < 8; ++j)
      cp16(base + B_OFF + (tid + j * 512) * 16, srcB + 2 * (tid + j * 512));
  };

  float acc[2][8][4];
  #pragma unroll
  for (int a = 0; a < 2; ++a)
    #pragma unroll
    for (int b = 0; b < 8; ++b)
      #pragma unroll
      for (int q = 0; q < 4; ++q) acc[a][b][q] = 0.f;

  // prologue: stage 0 in flight
  load_burst(0); cp_commit();

  for (int st = 0; st < NIT; ++st){
    cp_wait<0>();
    __syncthreads();   // stage st ready; all warps done with st-1 -> other buf free

    const uint4* As = (const uint4*)(smem + (st & 1) * STAGE_BYTES);
    const uint2* Bs = (const uint2*)(smem + (st & 1) * STAGE_BYTES + B_OFF);

    const bool pf = (st + 1 < NIT);
    uint32_t nbase = sb + ((st + 1) & 1) * STAGE_BYTES;
    const uint4* nA = gA + (size_t)(st + 1) * 2048;
    const uint2* nB = gB + (size_t)(st + 1) * 8192;

    #pragma unroll
    for (int kt = 0; kt < 8; ++kt){
      // spread next-stage cp.async: pattern 2,1,2,1,2,1,2,1 = 12 per thread
      if (pf){
        if ((kt & 1) == 0){
          int j = kt + (kt >> 1);        // 0,3,6,9 -> issue slots j, j+1
          // slots 0..3 = A, 4..11 = B
          #pragma unroll
          for (int s = 0; s < 2; ++s){
            int sl = j + s;
            if (sl < 4)
              cp16(nbase + (tid + sl * 512) * 16, nA + tid + sl * 512);
            else
              cp16(nbase + B_OFF + (tid + (sl - 4) * 512) * 16, nB + 2 * (tid + (sl - 4) * 512));
          }
        } else {
          int sl = kt + (kt >> 1);       // 1,4,7,10 -> +1 => slots 2,5,8,11
          sl += 1;
          if (sl < 4)
            cp16(nbase + (tid + sl * 512) * 16, nA + tid + sl * 512);
          else
            cp16(nbase + B_OFF + (tid + (sl - 4) * 512) * 16, nB + 2 * (tid + (sl - 4) * 512));
        }
      }

      uint2 bf[8];
      #pragma unroll
      for (int j = 0; j < 8; ++j)
        bf[j] = Bs[(kt * 32 + w_n * 8 + j) * 32 + T];
      uint4 af[2];
      #pragma unroll
      for (int mt = 0; mt < 2; ++mt)
        af[mt] = As[(kt * 8 + w_m * 2 + mt) * 32 + T];
      #pragma unroll
      for (int mt = 0; mt < 2; ++mt)
        #pragma unroll
        for (int j = 0; j < 8; ++j)
          mma16(acc[mt][j], af[mt], bf[j].x, bf[j].y);
    }
    cp_commit();   // one group per stage (empty for last stage is fine)
  }

  // -------- fused LSTM epilogue (register-local: gates g at acc[.][jc*4+g]) --------
  const size_t S = (size_t)B_SZ * 1024;

  float bias[2][4][2];
  #pragma unroll
  for (int jc = 0; jc < 2; ++jc){
    int col = nb * 64 + (w_n * 2 + jc) * 8 + (T & 3) * 2;
    #pragma unroll
    for (int g = 0; g < 4; ++g)
      #pragma unroll
      for (int cc = 0; cc < 2; ++cc)
        bias[jc][g][cc] = bx[g * 1024 + col + cc] + bh[g * 1024 + col + cc];
  }

  #pragma unroll
  for (int mt = 0; mt < 2; ++mt){
    #pragma unroll
    for (int jc = 0; jc < 2; ++jc){
      int col = nb * 64 + (w_n * 2 + jc) * 8 + (T & 3) * 2;
      #pragma unroll
      for (int rr = 0; rr < 2; ++rr){
        int row = mb * 128 + w_m * 32 + mt * 16 + (T >> 2) + rr * 8;
        size_t ro = (size_t)row * 1024 + col;
        float2 cin = *(const float2*)(c + ro);
        float2 o2, h2v, c2;
        #pragma unroll
        for (int cc = 0; cc < 2; ++cc){
          int q = rr * 2 + cc;
          float vi = acc[mt][jc * 4 + 0][q] + bias[jc][0][cc];
          float vf = acc[mt][jc * 4 + 1][q] + bias[jc][1][cc];
          float vg = acc[mt][jc * 4 + 2][q] + bias[jc][2][cc];
          float vo = acc[mt][jc * 4 + 3][q] + bias[jc][3][cc];
          float ig = sigmoidf_(vi);
          float fg = sigmoidf_(vf);
          float gg = tanhf(vg);
          float og = sigmoidf_(vo);
          float cv = (cc == 0) ? cin.x : cin.y;
          float cn = fg * cv + ig * gg;
          float hn = og * tanhf(cn);
          if (cc == 0){ o2.x = og; h2v.x = hn; c2.x = cn; }
          else        { o2.y = og; h2v.y = hn; c2.y = cn; }
        }
        *(float2*)(out + ro)         = o2;    // output gate
        *(float2*)(out + S + ro)     = h2v;   // h_new
        *(float2*)(out + 2 * S + ro) = c2;    // c_new
      }
    }
  }
}

// ---------------- launch ----------------
extern "C" void kernel_launch(void* const* d_in, const int* in_sizes, int n_in,
                              void* d_out, int out_size)
{
  const float* x  = (const float*)d_in[0];
  const float* h  = (const float*)d_in[1];
  const float* c  = (const float*)d_in[2];
  const float* Wx = (const float*)d_in[3];
  const float* Wh = (const float*)d_in[4];
  const float* bx = (const float*)d_in[5];
  const float* bh = (const float*)d_in[6];
  float* out = (float*)d_out;

  cudaFuncSetAttribute(lstm_main,
                       cudaFuncAttributeMaxDynamicSharedMemorySize, SMEM_TOTAL);

  prep_AB<<<16384, 256>>>(x, h, Wx, Wh);   // A-half + B-half in one launch
  lstm_main<<<dim3(16, 64), NTHREADS, SMEM_TOTAL>>>(c, bx, bh, out);
}